// round 1
// baseline (speedup 1.0000x reference)
#include <cuda_runtime.h>

#define CIN 128
#define C 64
#define H2f 0.01f
#define EB 8
#define NNODES 50000
#define NEDGES 800000

__device__ float g_deg[NNODES];
__device__ float g_W[NEDGES];
__device__ float g_buf[3][(long)NNODES * C];

__global__ void k_zero(int nN) {
    int i = blockIdx.x * blockDim.x + threadIdx.x;
    if (i < nN) g_deg[i] = 0.0f;
}

__global__ void k_degree(const int* __restrict__ Jv, int nE) {
    int e = blockIdx.x * blockDim.x + threadIdx.x;
    if (e < nE) atomicAdd(&g_deg[Jv[e]], 1.0f);
}

// deg includes the self-loop (+1); reuse g_deg as dinv
__global__ void k_dinv(int nN) {
    int i = blockIdx.x * blockDim.x + threadIdx.x;
    if (i < nN) g_deg[i] = rsqrtf(g_deg[i] + 1.0f);
}

__global__ void k_W(const int* __restrict__ Iv, const int* __restrict__ Jv, int nE) {
    int e = blockIdx.x * blockDim.x + threadIdx.x;
    if (e < nE) g_W[e] = g_deg[Iv[e]] * g_deg[Jv[e]];
}

// x0 = relu(K1 @ xn), written to buf0 (xn) and buf1 (xn_old)
__global__ void __launch_bounds__(256) k_proj(const float* __restrict__ xn,
                                              const float* __restrict__ K1, int nN) {
    __shared__ float Ks[C * CIN];
    __shared__ float xs[CIN * 64];
    int tid = threadIdx.x;
    for (int i = tid; i < C * CIN; i += 256) Ks[i] = K1[i];
    int n0 = blockIdx.x * 64;
    for (int i = tid; i < CIN * 64; i += 256) {
        int k = i >> 6, nl = i & 63;
        int n = n0 + nl;
        xs[i] = (n < nN) ? xn[(long)k * nN + n] : 0.0f;
    }
    __syncthreads();
    int nl = tid & 63;
    int cb = (tid >> 6) * 16;
    float acc[16];
#pragma unroll
    for (int j = 0; j < 16; j++) acc[j] = 0.0f;
    for (int k = 0; k < CIN; k++) {
        float xv = xs[k * 64 + nl];
#pragma unroll
        for (int j = 0; j < 16; j++) acc[j] = fmaf(Ks[(cb + j) * CIN + k], xv, acc[j]);
    }
    int n = n0 + nl;
    if (n < nN) {
#pragma unroll
        for (int j = 0; j < 16; j++) {
            float v = fmaxf(acc[j], 0.0f);
            g_buf[0][(long)n * C + cb + j] = v;
            g_buf[1][(long)n * C + cb + j] = v;
        }
    }
}

// A = 2*x_cur - x_old  (edge kernel then red-adds -H^2*dxn into A)
__global__ void k_init(int curI, int oldI, int nxtI, int n4) {
    int i = blockIdx.x * blockDim.x + threadIdx.x;
    if (i >= n4) return;
    const float4* xc = (const float4*)g_buf[curI];
    const float4* xo = (const float4*)g_buf[nxtI == curI ? oldI : oldI];
    float4* A = (float4*)g_buf[nxtI];
    float4 a = xc[i], b = ((const float4*)g_buf[oldI])[i];
    (void)xo;
    A[i] = make_float4(2.0f * a.x - b.x, 2.0f * a.y - b.y,
                       2.0f * a.z - b.z, 2.0f * a.w - b.w);
}

// Hot kernel: warp handles EB=8 edges; two 64x64 GEMVs per edge from smem K.
__global__ void __launch_bounds__(256, 3) k_edge(int xI, int aI,
        const int* __restrict__ Iv, const int* __restrict__ Jv,
        const float* __restrict__ Km, int nE)
{
    __shared__ float Ktp[C * C];           // Ktp[c*64 + 2L + h] = K[L+32h][c]  (GEMM1)
    __shared__ float Ktr[C * C];           // Ktr[o*64 + c]      = K[c][o]      (GEMM2)
    __shared__ float sbuf[8 * EB * C];     // per-warp g/t staging (2KB per warp)
    int tid = threadIdx.x;
    for (int i = tid; i < C * C; i += 256) {
        float v = Km[i];
        int r = i >> 6, q = i & 63;
        Ktp[q * 64 + 2 * (r & 31) + (r >> 5)] = v;
        Ktr[q * 64 + r] = v;
    }
    __syncthreads();
    const float2* x2 = (const float2*)g_buf[xI];
    float* A = g_buf[aI];
    int lane = tid & 31;
    int wid = tid >> 5;
    float* sb = sbuf + wid * (EB * C);
    const float2* Ktp2 = (const float2*)Ktp;
    const float2* Ktr2 = (const float2*)Ktr;
    long gw = (long)blockIdx.x * 8 + wid;
    long nW = (long)gridDim.x * 8;
    for (long e0 = gw * EB; e0 < nE; e0 += nW * EB) {
        int ii = 0, jj = 0; float ww = 0.0f;
        if (lane < EB && e0 + lane < (long)nE) {
            ii = Iv[e0 + lane];
            jj = Jv[e0 + lane];
            ww = g_W[e0 + lane];
        }
        // gather: g = W*(x_I - x_J), lane holds channels (2L, 2L+1)
#pragma unroll
        for (int e = 0; e < EB; e++) {
            int i = __shfl_sync(0xffffffffu, ii, e);
            int j = __shfl_sync(0xffffffffu, jj, e);
            float w = __shfl_sync(0xffffffffu, ww, e);
            float2 xi = x2[(long)i * 32 + lane];
            float2 xj = x2[(long)j * 32 + lane];
            ((float2*)sb)[e * 32 + lane] =
                make_float2(w * (xi.x - xj.x), w * (xi.y - xj.y));
        }
        __syncwarp();
        // GEMM1: t[o] = sum_c K[o][c]*g[c]; lane computes o = lane, lane+32
        float t0[EB], t1[EB];
#pragma unroll
        for (int e = 0; e < EB; e++) { t0[e] = 0.0f; t1[e] = 0.0f; }
#pragma unroll 4
        for (int c = 0; c < C; c++) {
            float2 kv = Ktp2[c * 32 + lane];   // (K[lane][c], K[lane+32][c])
#pragma unroll
            for (int e = 0; e < EB; e++) {
                float gc = sb[e * C + c];
                t0[e] = fmaf(kv.x, gc, t0[e]);
                t1[e] = fmaf(kv.y, gc, t1[e]);
            }
        }
        __syncwarp();
#pragma unroll
        for (int e = 0; e < EB; e++) {
            sb[e * C + lane]      = tanhf(t0[e]);
            sb[e * C + lane + 32] = tanhf(t1[e]);
        }
        __syncwarp();
        // GEMM2: d[c] = sum_o K[c][o]*t[o]; lane computes c = 2L, 2L+1
        float d0[EB], d1[EB];
#pragma unroll
        for (int e = 0; e < EB; e++) { d0[e] = 0.0f; d1[e] = 0.0f; }
#pragma unroll 4
        for (int o = 0; o < C; o++) {
            float2 kv = Ktr2[o * 32 + lane];   // (K[2L][o], K[2L+1][o])
#pragma unroll
            for (int e = 0; e < EB; e++) {
                float tv = sb[e * C + o];
                d0[e] = fmaf(kv.x, tv, d0[e]);
                d1[e] = fmaf(kv.y, tv, d1[e]);
            }
        }
        // scatter: A[I] -= H^2*W*d ; A[J] += H^2*W*d  (vector red, 2 instr/edge)
#pragma unroll
        for (int e = 0; e < EB; e++) {
            if (e0 + e < (long)nE) {
                int i = __shfl_sync(0xffffffffu, ii, e);
                int j = __shfl_sync(0xffffffffu, jj, e);
                float w = __shfl_sync(0xffffffffu, ww, e);
                float sc = H2f * w;
                float a0 = sc * d0[e], a1 = sc * d1[e];
                float* pi = A + (long)i * C + 2 * lane;
                float* pj = A + (long)j * C + 2 * lane;
                asm volatile("red.global.add.v2.f32 [%0], {%1, %2};"
                             :: "l"(pi), "f"(-a0), "f"(-a1) : "memory");
                asm volatile("red.global.add.v2.f32 [%0], {%1, %2};"
                             :: "l"(pj), "f"(a0), "f"(a1) : "memory");
            }
        }
        __syncwarp();
    }
}

// out[n][o] = sum_c KNclose[o][c] * x[n][c]
__global__ void __launch_bounds__(128) k_out(int xIdx, const float* __restrict__ KNc,
                                             float* __restrict__ out, int nN, int nOut) {
    __shared__ float Ks[40 * C];
    for (int i = threadIdx.x; i < nOut * C; i += 128) Ks[i] = KNc[i];
    __syncthreads();
    int n = blockIdx.x * 128 + threadIdx.x;
    if (n >= nN) return;
    const float* xr = g_buf[xIdx] + (long)n * C;
    float xv[C];
#pragma unroll
    for (int q = 0; q < C / 4; q++) {
        float4 v = ((const float4*)xr)[q];
        xv[4 * q] = v.x; xv[4 * q + 1] = v.y; xv[4 * q + 2] = v.z; xv[4 * q + 3] = v.w;
    }
    for (int o = 0; o < nOut; o++) {
        float acc = 0.0f;
#pragma unroll
        for (int c = 0; c < C; c++) acc = fmaf(Ks[o * C + c], xv[c], acc);
        out[(long)n * nOut + o] = acc;
    }
}

extern "C" void kernel_launch(void* const* d_in, const int* in_sizes, int n_in,
                              void* d_out, int out_size) {
    const float* xn = (const float*)d_in[0];
    const int* Iv = (const int*)d_in[1];
    const int* Jv = (const int*)d_in[2];
    int idx = 3;
    if (n_in >= 7 && in_sizes[3] == 1) idx = 4;   // skip scalar n_nodes input
    const float* K1  = (const float*)d_in[idx];
    const float* KN2 = (const float*)d_in[idx + 1];
    const float* KNc = (const float*)d_in[idx + 2];
    int nE = in_sizes[1];
    int nN = in_sizes[0] / CIN;
    int nLayer = in_sizes[idx + 1] / (C * C);
    int nOut = in_sizes[idx + 2] / C;
    float* out = (float*)d_out;

    k_zero<<<(nN + 255) / 256, 256>>>(nN);
    k_degree<<<(nE + 255) / 256, 256>>>(Jv, nE);
    k_dinv<<<(nN + 255) / 256, 256>>>(nN);
    k_W<<<(nE + 255) / 256, 256>>>(Iv, Jv, nE);
    k_proj<<<(nN + 63) / 64, 256>>>(xn, K1, nN);

    int cur = 0, old = 1, nxt = 2;
    int n4 = nN * C / 4;
    for (int l = 0; l < nLayer; l++) {
        k_init<<<(n4 + 255) / 256, 256>>>(cur, old, nxt, n4);
        k_edge<<<912, 256>>>(cur, nxt, Iv, Jv, KN2 + (long)l * C * C, nE);
        int t = old; old = cur; cur = nxt; nxt = t;
    }
    k_out<<<(nN + 127) / 128, 128>>>(cur, KNc, out, nN, nOut);
}

// round 2
// speedup vs baseline: 1.0344x; 1.0344x over previous
#include <cuda_runtime.h>

#define CIN 128
#define C 64
#define H2f 0.01f
#define EB 8
#define NNODES 50000
#define NEDGES 800000

__device__ float g_deg[NNODES];
__device__ float g_W[NEDGES];
__device__ float g_buf[3][(long)NNODES * C];

// ---- helpers: packed f32x2 ----
__device__ __forceinline__ unsigned long long dup2(float x) {
    unsigned long long d;
    asm("mov.b64 %0, {%1, %1};" : "=l"(d) : "f"(x));
    return d;
}
__device__ __forceinline__ void ffma2(unsigned long long& acc,
                                      unsigned long long a, unsigned long long b) {
    asm("fma.rn.f32x2 %0, %1, %2, %0;" : "+l"(acc) : "l"(a), "l"(b));
}
__device__ __forceinline__ float2 u2f2(unsigned long long u) {
    float2 f;
    asm("mov.b64 {%0, %1}, %2;" : "=f"(f.x), "=f"(f.y) : "l"(u));
    return f;
}
__device__ __forceinline__ float tanh_fast(float x) {
    float y;
    asm("tanh.approx.f32 %0, %1;" : "=f"(y) : "f"(x));
    return y;
}

__global__ void k_zero(int nN) {
    int i = blockIdx.x * blockDim.x + threadIdx.x;
    if (i < nN) g_deg[i] = 0.0f;
}

__global__ void k_degree(const int* __restrict__ Jv, int nE) {
    int e = blockIdx.x * blockDim.x + threadIdx.x;
    if (e < nE) atomicAdd(&g_deg[Jv[e]], 1.0f);
}

__global__ void k_dinv(int nN) {
    int i = blockIdx.x * blockDim.x + threadIdx.x;
    if (i < nN) g_deg[i] = rsqrtf(g_deg[i] + 1.0f);
}

__global__ void k_W(const int* __restrict__ Iv, const int* __restrict__ Jv, int nE) {
    int e = blockIdx.x * blockDim.x + threadIdx.x;
    if (e < nE) g_W[e] = g_deg[Iv[e]] * g_deg[Jv[e]];
}

// x0 = relu(K1 @ xn) -> buf0 (xn) and buf1 (xn_old)
__global__ void __launch_bounds__(256) k_proj(const float* __restrict__ xn,
                                              const float* __restrict__ K1, int nN) {
    __shared__ float Ks[C * CIN];
    __shared__ float xs[CIN * 64];
    int tid = threadIdx.x;
    for (int i = tid; i < C * CIN; i += 256) Ks[i] = K1[i];
    int n0 = blockIdx.x * 64;
    for (int i = tid; i < CIN * 64; i += 256) {
        int k = i >> 6, nl = i & 63;
        int n = n0 + nl;
        xs[i] = (n < nN) ? xn[(long)k * nN + n] : 0.0f;
    }
    __syncthreads();
    int nl = tid & 63;
    int cb = (tid >> 6) * 16;
    float acc[16];
#pragma unroll
    for (int j = 0; j < 16; j++) acc[j] = 0.0f;
    for (int k = 0; k < CIN; k++) {
        float xv = xs[k * 64 + nl];
#pragma unroll
        for (int j = 0; j < 16; j++) acc[j] = fmaf(Ks[(cb + j) * CIN + k], xv, acc[j]);
    }
    int n = n0 + nl;
    if (n < nN) {
#pragma unroll
        for (int j = 0; j < 16; j++) {
            float v = fmaxf(acc[j], 0.0f);
            g_buf[0][(long)n * C + cb + j] = v;
            g_buf[1][(long)n * C + cb + j] = v;
        }
    }
}

// A = 2*x_cur - x_old
__global__ void k_init(int curI, int oldI, int nxtI, int n4) {
    int i = blockIdx.x * blockDim.x + threadIdx.x;
    if (i >= n4) return;
    float4 a = ((const float4*)g_buf[curI])[i];
    float4 b = ((const float4*)g_buf[oldI])[i];
    ((float4*)g_buf[nxtI])[i] = make_float4(2.0f * a.x - b.x, 2.0f * a.y - b.y,
                                            2.0f * a.z - b.z, 2.0f * a.w - b.w);
}

// Hot kernel. Warp handles EB=8 edges. Both 64x64 GEMVs use packed
// fma.rn.f32x2 with the accumulator packed over edge pairs; g/t staged
// in a per-warp swizzled smem tile (rows of 8 floats, col = e ^ 2*((row>>2)&3)).
__global__ void __launch_bounds__(256, 3) k_edge(int xI, int aI,
        const int* __restrict__ Iv, const int* __restrict__ Jv,
        const float* __restrict__ Km, int nE)
{
    __shared__ float Ktp[C * C];        // Ktp[c*64 + 2L + h] = K[L+32h][c]
    __shared__ float Ktr[C * C];        // Ktr[o*64 + c]      = K[c][o]
    __shared__ float sbuf[8][C * EB];   // per-warp staging (swizzled)
    int tid = threadIdx.x;
    for (int i = tid; i < C * C; i += 256) {
        float v = Km[i];
        int r = i >> 6, q = i & 63;
        Ktp[q * 64 + 2 * (r & 31) + (r >> 5)] = v;
        Ktr[q * 64 + r] = v;
    }
    __syncthreads();
    const float2* x2 = (const float2*)g_buf[xI];
    float* A = g_buf[aI];
    int lane = tid & 31;
    int wid = tid >> 5;
    float* sb = sbuf[wid];
    const float2* Ktp2 = (const float2*)Ktp;
    const float2* Ktr2 = (const float2*)Ktr;
    long gw = (long)blockIdx.x * 8 + wid;
    long nW = (long)gridDim.x * 8;
    int swg = lane >> 1;                // (c>>2) for c = 2*lane : swizzle row group
    for (long e0 = gw * EB; e0 < nE; e0 += nW * EB) {
        int ii = 0, jj = 0; float ww = 0.0f;
        if (lane < EB && e0 + lane < (long)nE) {
            ii = Iv[e0 + lane];
            jj = Jv[e0 + lane];
            ww = g_W[e0 + lane];
        }
        // ---- gather: g[c][e] = W*(x_I - x_J), rows c = 2L, 2L+1 ----
        int sg = 2 * (swg & 3);
#pragma unroll
        for (int e = 0; e < EB; e++) {
            int i = __shfl_sync(0xffffffffu, ii, e);
            int j = __shfl_sync(0xffffffffu, jj, e);
            float w = __shfl_sync(0xffffffffu, ww, e);
            float2 xi = x2[(long)i * 32 + lane];
            float2 xj = x2[(long)j * 32 + lane];
            int col = e ^ sg;
            sb[(2 * lane) * EB + col]     = w * (xi.x - xj.x);
            sb[(2 * lane) * EB + EB + col] = w * (xi.y - xj.y);
        }
        __syncwarp();
        // ---- GEMM1: t[o][e] = sum_c K[o][c] * g[c][e]; o = lane, lane+32 ----
        unsigned long long acc0[EB / 2], acc1[EB / 2];
#pragma unroll
        for (int p = 0; p < EB / 2; p++) { acc0[p] = 0ull; acc1[p] = 0ull; }
#pragma unroll 4
        for (int c = 0; c < C; c++) {
            float2 kv = Ktp2[c * 32 + lane];   // (K[lane][c], K[lane+32][c])
            unsigned long long kx = dup2(kv.x);
            unsigned long long ky = dup2(kv.y);
            const unsigned long long* gr = (const unsigned long long*)(sb + c * EB);
            int sw = (c >> 2) & 3;
#pragma unroll
            for (int p = 0; p < EB / 2; p++) {
                unsigned long long gp = gr[p ^ sw];   // broadcast: (g[c][2p], g[c][2p+1])
                ffma2(acc0[p], kx, gp);
                ffma2(acc1[p], ky, gp);
            }
        }
        __syncwarp();
        // ---- tanh, store t transposed into same buffer ----
        {
            int swo0 = 2 * ((lane >> 2) & 3);   // swizzle for rows o=lane and o=lane+32
#pragma unroll
            for (int p = 0; p < EB / 2; p++) {
                float2 a = u2f2(acc0[p]);
                float2 b = u2f2(acc1[p]);
                int c0 = (2 * p) ^ swo0, c1 = (2 * p + 1) ^ swo0;
                sb[lane * EB + c0] = tanh_fast(a.x);
                sb[lane * EB + c1] = tanh_fast(a.y);
                sb[(lane + 32) * EB + c0] = tanh_fast(b.x);
                sb[(lane + 32) * EB + c1] = tanh_fast(b.y);
            }
        }
        __syncwarp();
        // ---- GEMM2: d[c][e] = sum_o K[c][o] * t[o][e]; c = 2L, 2L+1 ----
        unsigned long long d0[EB / 2], d1[EB / 2];
#pragma unroll
        for (int p = 0; p < EB / 2; p++) { d0[p] = 0ull; d1[p] = 0ull; }
#pragma unroll 4
        for (int o = 0; o < C; o++) {
            float2 kv = Ktr2[o * 32 + lane];   // (K[2L][o], K[2L+1][o])
            unsigned long long kx = dup2(kv.x);
            unsigned long long ky = dup2(kv.y);
            const unsigned long long* tr = (const unsigned long long*)(sb + o * EB);
            int sw = (o >> 2) & 3;
#pragma unroll
            for (int p = 0; p < EB / 2; p++) {
                unsigned long long tp = tr[p ^ sw];
                ffma2(d0[p], kx, tp);
                ffma2(d1[p], ky, tp);
            }
        }
        // ---- scatter: A[I] -= H^2*W*d ; A[J] += H^2*W*d ----
#pragma unroll
        for (int p = 0; p < EB / 2; p++) {
            float2 da = u2f2(d0[p]);   // c=2L : edges 2p, 2p+1
            float2 db = u2f2(d1[p]);   // c=2L+1
#pragma unroll
            for (int h = 0; h < 2; h++) {
                int e = 2 * p + h;
                if (e0 + e < (long)nE) {
                    int i = __shfl_sync(0xffffffffu, ii, e);
                    int j = __shfl_sync(0xffffffffu, jj, e);
                    float w = __shfl_sync(0xffffffffu, ww, e);
                    float sc = H2f * w;
                    float a0 = sc * (h ? da.y : da.x);
                    float a1 = sc * (h ? db.y : db.x);
                    float* pi = A + (long)i * C + 2 * lane;
                    float* pj = A + (long)j * C + 2 * lane;
                    asm volatile("red.global.add.v2.f32 [%0], {%1, %2};"
                                 :: "l"(pi), "f"(-a0), "f"(-a1) : "memory");
                    asm volatile("red.global.add.v2.f32 [%0], {%1, %2};"
                                 :: "l"(pj), "f"(a0), "f"(a1) : "memory");
                }
            }
        }
        __syncwarp();
    }
}

// out[n][o] = sum_c KNclose[o][c] * x[n][c]
__global__ void __launch_bounds__(128) k_out(int xIdx, const float* __restrict__ KNc,
                                             float* __restrict__ out, int nN, int nOut) {
    __shared__ float Ks[40 * C];
    for (int i = threadIdx.x; i < nOut * C; i += 128) Ks[i] = KNc[i];
    __syncthreads();
    int n = blockIdx.x * 128 + threadIdx.x;
    if (n >= nN) return;
    const float* xr = g_buf[xIdx] + (long)n * C;
    float xv[C];
#pragma unroll
    for (int q = 0; q < C / 4; q++) {
        float4 v = ((const float4*)xr)[q];
        xv[4 * q] = v.x; xv[4 * q + 1] = v.y; xv[4 * q + 2] = v.z; xv[4 * q + 3] = v.w;
    }
    for (int o = 0; o < nOut; o++) {
        float acc = 0.0f;
#pragma unroll
        for (int c = 0; c < C; c++) acc = fmaf(Ks[o * C + c], xv[c], acc);
        out[(long)n * nOut + o] = acc;
    }
}

extern "C" void kernel_launch(void* const* d_in, const int* in_sizes, int n_in,
                              void* d_out, int out_size) {
    const float* xn = (const float*)d_in[0];
    const int* Iv = (const int*)d_in[1];
    const int* Jv = (const int*)d_in[2];
    int idx = 3;
    if (n_in >= 7 && in_sizes[3] == 1) idx = 4;   // skip scalar n_nodes input
    const float* K1  = (const float*)d_in[idx];
    const float* KN2 = (const float*)d_in[idx + 1];
    const float* KNc = (const float*)d_in[idx + 2];
    int nE = in_sizes[1];
    int nN = in_sizes[0] / CIN;
    int nLayer = in_sizes[idx + 1] / (C * C);
    int nOut = in_sizes[idx + 2] / C;
    float* out = (float*)d_out;

    k_zero<<<(nN + 255) / 256, 256>>>(nN);
    k_degree<<<(nE + 255) / 256, 256>>>(Jv, nE);
    k_dinv<<<(nN + 255) / 256, 256>>>(nN);
    k_W<<<(nE + 255) / 256, 256>>>(Iv, Jv, nE);
    k_proj<<<(nN + 63) / 64, 256>>>(xn, K1, nN);

    int cur = 0, old = 1, nxt = 2;
    int n4 = nN * C / 4;
    for (int l = 0; l < nLayer; l++) {
        k_init<<<(n4 + 255) / 256, 256>>>(cur, old, nxt, n4);
        k_edge<<<912, 256>>>(cur, nxt, Iv, Jv, KN2 + (long)l * C * C, nE);
        int t = old; old = cur; cur = nxt; nxt = t;
    }
    k_out<<<(nN + 127) / 128, 128>>>(cur, KNc, out, nN, nOut);
}